// round 3
// baseline (speedup 1.0000x reference)
#include <cuda_runtime.h>

// CTPN loss: H=512, W=1024, K=10, N_POS=N_NEG=64.
// Single-warp latency-optimized version: 32 threads, 4 anchors each,
// vectorized index/target loads, intrinsic CE, pure-shuffle reduction.
// Output: 4 f32 = (loss, avg_loss_cls, avg_loss_reg_v, avg_loss_reg_o)

#define HW_ (512 * 1024)
#define W_  1024

__device__ __forceinline__ float smooth_l1(float d) {
    float a = fabsf(d);
    return (a < 1.0f) ? 0.5f * a * a : a - 0.5f;
}

// -log_softmax over 2 logits (s0,s1), target class given by sign convention:
//   pos (target=1): relu(d) + log1p(exp(-|d|)),  d = s0 - s1
//   neg (target=0): relu(-d) + log1p(exp(-|d|))
__device__ __forceinline__ float ce_term(float d_signed, float d_abs) {
    return fmaxf(d_signed, 0.0f) + __logf(1.0f + __expf(-d_abs));
}

__global__ void ctpn_loss_kernel(
    const float* __restrict__ scores,
    const float* __restrict__ vcoords,
    const float* __restrict__ sides,
    const int* __restrict__ pos_y, const int* __restrict__ pos_x, const int* __restrict__ pos_z,
    const int* __restrict__ neg_y, const int* __restrict__ neg_x, const int* __restrict__ neg_z,
    const float* __restrict__ v_targets,
    const int* __restrict__ side_mask,
    const float* __restrict__ side_targets,
    float* __restrict__ out, int out_size)
{
    const int t = threadIdx.x;          // 0..31

    float cls = 0.0f, vsum = 0.0f, osum = 0.0f, cnt = 0.0f;

    if (t < 16) {
        // ---- positive anchors 4t..4t+3 ----
        const int4 ys = ((const int4*)pos_y)[t];
        const int4 xs = ((const int4*)pos_x)[t];
        const int4 zs = ((const int4*)pos_z)[t];
        const float4 vt0 = ((const float4*)v_targets)[2 * t];
        const float4 vt1 = ((const float4*)v_targets)[2 * t + 1];
        const int4   sm  = ((const int4*)side_mask)[t];
        const float4 st  = ((const float4*)side_targets)[t];

        const int ya[4] = {ys.x, ys.y, ys.z, ys.w};
        const int xa[4] = {xs.x, xs.y, xs.z, xs.w};
        const int za[4] = {zs.x, zs.y, zs.z, zs.w};
        const float vta[8] = {vt0.x, vt0.y, vt0.z, vt0.w, vt1.x, vt1.y, vt1.z, vt1.w};
        const int   sma[4] = {sm.x, sm.y, sm.z, sm.w};
        const float sta[4] = {st.x, st.y, st.z, st.w};

        #pragma unroll
        for (int j = 0; j < 4; j++) {
            const unsigned base  = (unsigned)(2 * za[j]) * HW_ + (unsigned)ya[j] * W_ + (unsigned)xa[j];
            const unsigned sbase = (unsigned)za[j] * HW_ + (unsigned)ya[j] * W_ + (unsigned)xa[j];

            const float s0 = __ldg(scores + base);
            const float s1 = __ldg(scores + base + HW_);
            const float v0 = __ldg(vcoords + base);
            const float v1 = __ldg(vcoords + base + HW_);
            const float sp = __ldg(sides + sbase);

            const float d = s0 - s1;
            cls += ce_term(d, fabsf(d));                       // target = 1

            vsum += smooth_l1(v0 - vta[2 * j]) + smooth_l1(v1 - vta[2 * j + 1]);

            const float mm = (float)sma[j];
            osum += smooth_l1(sp - sta[j]) * mm;
            cnt  += mm;
        }
    } else {
        // ---- negative anchors 4(t-16)..+3 ----
        const int i = t - 16;
        const int4 ys = ((const int4*)neg_y)[i];
        const int4 xs = ((const int4*)neg_x)[i];
        const int4 zs = ((const int4*)neg_z)[i];

        const int ya[4] = {ys.x, ys.y, ys.z, ys.w};
        const int xa[4] = {xs.x, xs.y, xs.z, xs.w};
        const int za[4] = {zs.x, zs.y, zs.z, zs.w};

        #pragma unroll
        for (int j = 0; j < 4; j++) {
            const unsigned base = (unsigned)(2 * za[j]) * HW_ + (unsigned)ya[j] * W_ + (unsigned)xa[j];
            const float s0 = __ldg(scores + base);
            const float s1 = __ldg(scores + base + HW_);
            const float d = s0 - s1;
            cls += ce_term(-d, fabsf(d));                      // target = 0
        }
    }

    // ---- warp butterfly reduction, 4 accumulators ----
    #pragma unroll
    for (int off = 16; off > 0; off >>= 1) {
        cls  += __shfl_xor_sync(0xFFFFFFFFu, cls,  off);
        vsum += __shfl_xor_sync(0xFFFFFFFFu, vsum, off);
        osum += __shfl_xor_sync(0xFFFFFFFFu, osum, off);
        cnt  += __shfl_xor_sync(0xFFFFFFFFu, cnt,  off);
    }

    if (t == 0) {
        const float avg_cls = cls  * (1.0f / 128.0f);
        const float avg_v   = vsum * (1.0f / 128.0f);   // 64 anchors * 2 comps
        const float avg_o   = (cnt > 0.0f) ? osum / fmaxf(cnt, 1.0f) : 0.0f;
        const float loss    = avg_cls + avg_v + 2.0f * avg_o;

        if (out_size >= 4) {
            float4 o4 = make_float4(loss, avg_cls, avg_v, avg_o);
            *(float4*)out = o4;
        } else {
            if (out_size > 0) out[0] = loss;
            if (out_size > 1) out[1] = avg_cls;
            if (out_size > 2) out[2] = avg_v;
            if (out_size > 3) out[3] = avg_o;
        }
    }
}

extern "C" void kernel_launch(void* const* d_in, const int* in_sizes, int n_in,
                              void* d_out, int out_size) {
    const float* scores       = (const float*)d_in[0];
    const float* vcoords      = (const float*)d_in[1];
    const float* sides        = (const float*)d_in[2];
    const int*   pos_y        = (const int*)d_in[3];
    const int*   pos_x        = (const int*)d_in[4];
    const int*   pos_z        = (const int*)d_in[5];
    const int*   neg_y        = (const int*)d_in[6];
    const int*   neg_x        = (const int*)d_in[7];
    const int*   neg_z        = (const int*)d_in[8];
    const float* v_targets    = (const float*)d_in[9];
    const int*   side_mask    = (const int*)d_in[10];
    const float* side_targets = (const float*)d_in[11];

    ctpn_loss_kernel<<<1, 32>>>(scores, vcoords, sides,
                                pos_y, pos_x, pos_z,
                                neg_y, neg_x, neg_z,
                                v_targets, side_mask, side_targets,
                                (float*)d_out, out_size);
}

// round 4
// speedup vs baseline: 1.3077x; 1.3077x over previous
#include <cuda_runtime.h>

// CTPN loss: H=512, W=1024, K=10, N_POS=N_NEG=64.
// 128 threads (max MLP: 1 anchor/thread), intrinsic CE, 1-barrier reduction.
// Output: 4 f32 = (loss, avg_loss_cls, avg_loss_reg_v, avg_loss_reg_o)

#define HW_ (512u * 1024u)
#define W_  1024u

__device__ __forceinline__ float smooth_l1(float d) {
    float a = fabsf(d);
    return (a < 1.0f) ? 0.5f * a * a : a - 0.5f;
}

// -log_softmax over 2 logits with d = s_other - s_target:
//   = relu(d) + log(1 + exp(-|d|))
__device__ __forceinline__ float ce_term(float d) {
    return fmaxf(d, 0.0f) + __logf(1.0f + __expf(-fabsf(d)));
}

__global__ void ctpn_loss_kernel(
    const float* __restrict__ scores,
    const float* __restrict__ vcoords,
    const float* __restrict__ sides,
    const int* __restrict__ pos_y, const int* __restrict__ pos_x, const int* __restrict__ pos_z,
    const int* __restrict__ neg_y, const int* __restrict__ neg_x, const int* __restrict__ neg_z,
    const float* __restrict__ v_targets,
    const int* __restrict__ side_mask,
    const float* __restrict__ side_targets,
    float* __restrict__ out, int out_size)
{
    const int tid = threadIdx.x;        // 0..127

    float cls = 0.0f, vsum = 0.0f, osum = 0.0f, cnt = 0.0f;

    if (tid < 64) {
        // ---- positive anchor tid ----
        const int y = __ldg(pos_y + tid);
        const int x = __ldg(pos_x + tid);
        const int z = __ldg(pos_z + tid);
        const unsigned base  = (unsigned)(2 * z) * HW_ + (unsigned)y * W_ + (unsigned)x;
        const unsigned sbase = (unsigned)z * HW_ + (unsigned)y * W_ + (unsigned)x;

        // issue all independent loads up front
        const float s0  = __ldg(scores  + base);
        const float s1  = __ldg(scores  + base + HW_);
        const float v0  = __ldg(vcoords + base);
        const float v1  = __ldg(vcoords + base + HW_);
        const float sp  = __ldg(sides   + sbase);
        const float2 vt = __ldg((const float2*)v_targets + tid);
        const float mm  = (float)__ldg(side_mask + tid);
        const float st  = __ldg(side_targets + tid);

        cls  = ce_term(s0 - s1);                         // target = 1
        vsum = smooth_l1(v0 - vt.x) + smooth_l1(v1 - vt.y);
        osum = smooth_l1(sp - st) * mm;
        cnt  = mm;
    } else {
        // ---- negative anchor tid-64, target = 0 ----
        const int i = tid - 64;
        const int y = __ldg(neg_y + i);
        const int x = __ldg(neg_x + i);
        const int z = __ldg(neg_z + i);
        const unsigned base = (unsigned)(2 * z) * HW_ + (unsigned)y * W_ + (unsigned)x;
        const float s0 = __ldg(scores + base);
        const float s1 = __ldg(scores + base + HW_);
        cls = ce_term(s1 - s0);
    }

    // ---- per-warp shuffle reduction (4 accumulators) ----
    #pragma unroll
    for (int off = 16; off > 0; off >>= 1) {
        cls  += __shfl_xor_sync(0xFFFFFFFFu, cls,  off);
        vsum += __shfl_xor_sync(0xFFFFFFFFu, vsum, off);
        osum += __shfl_xor_sync(0xFFFFFFFFu, osum, off);
        cnt  += __shfl_xor_sync(0xFFFFFFFFu, cnt,  off);
    }

    // ---- cross-warp combine: 4 warps -> smem -> thread 0 ----
    __shared__ float4 part[4];
    if ((tid & 31) == 0)
        part[tid >> 5] = make_float4(cls, vsum, osum, cnt);
    __syncthreads();

    if (tid == 0) {
        float a = 0.0f, b = 0.0f, c = 0.0f, d = 0.0f;
        #pragma unroll
        for (int w = 0; w < 4; w++) {
            a += part[w].x; b += part[w].y; c += part[w].z; d += part[w].w;
        }
        const float avg_cls = a * (1.0f / 128.0f);
        const float avg_v   = b * (1.0f / 128.0f);   // 64 anchors * 2 comps
        const float avg_o   = (d > 0.0f) ? c / fmaxf(d, 1.0f) : 0.0f;
        const float loss    = avg_cls + avg_v + 2.0f * avg_o;

        if (out_size >= 4) {
            *(float4*)out = make_float4(loss, avg_cls, avg_v, avg_o);
        } else {
            if (out_size > 0) out[0] = loss;
            if (out_size > 1) out[1] = avg_cls;
            if (out_size > 2) out[2] = avg_v;
            if (out_size > 3) out[3] = avg_o;
        }
    }
}

extern "C" void kernel_launch(void* const* d_in, const int* in_sizes, int n_in,
                              void* d_out, int out_size) {
    const float* scores       = (const float*)d_in[0];
    const float* vcoords      = (const float*)d_in[1];
    const float* sides        = (const float*)d_in[2];
    const int*   pos_y        = (const int*)d_in[3];
    const int*   pos_x        = (const int*)d_in[4];
    const int*   pos_z        = (const int*)d_in[5];
    const int*   neg_y        = (const int*)d_in[6];
    const int*   neg_x        = (const int*)d_in[7];
    const int*   neg_z        = (const int*)d_in[8];
    const float* v_targets    = (const float*)d_in[9];
    const int*   side_mask    = (const int*)d_in[10];
    const float* side_targets = (const float*)d_in[11];

    ctpn_loss_kernel<<<1, 128>>>(scores, vcoords, sides,
                                 pos_y, pos_x, pos_z,
                                 neg_y, neg_x, neg_z,
                                 v_targets, side_mask, side_targets,
                                 (float*)d_out, out_size);
}

// round 7
// speedup vs baseline: 1.3399x; 1.0246x over previous
#include <cuda_runtime.h>

// CTPN loss: H=512, W=1024, K=10, N_POS=N_NEG=64.
// 128 threads, 1 anchor/thread (max MLP). Warps 0-1 = pos, warps 2-3 = neg.
// Neg warps reduce only cls. Single barrier, STG.128 output.
// Output: 4 f32 = (loss, avg_loss_cls, avg_loss_reg_v, avg_loss_reg_o)

#define HW_ (512u * 1024u)
#define W_  1024u

__device__ __forceinline__ float smooth_l1(float d) {
    float a = fabsf(d);
    return (a < 1.0f) ? 0.5f * a * a : a - 0.5f;
}

// -log_softmax over 2 logits with d = s_other - s_target:
//   = relu(d) + log(1 + exp(-|d|))
__device__ __forceinline__ float ce_term(float d) {
    return fmaxf(d, 0.0f) + __logf(1.0f + __expf(-fabsf(d)));
}

__global__ void __launch_bounds__(128, 1) ctpn_loss_kernel(
    const float* __restrict__ scores,
    const float* __restrict__ vcoords,
    const float* __restrict__ sides,
    const int* __restrict__ pos_y, const int* __restrict__ pos_x, const int* __restrict__ pos_z,
    const int* __restrict__ neg_y, const int* __restrict__ neg_x, const int* __restrict__ neg_z,
    const float* __restrict__ v_targets,
    const int* __restrict__ side_mask,
    const float* __restrict__ side_targets,
    float* __restrict__ out, int out_size)
{
    const int tid = threadIdx.x;        // 0..127
    const int wid = tid >> 5;           // 0..3

    __shared__ float s_cls[4];
    __shared__ float s_v[2], s_o[2], s_c[2];

    float cls;

    if (tid < 64) {
        // ---- positive anchor tid (warps 0-1) ----
        const int y = __ldg(pos_y + tid);
        const int x = __ldg(pos_x + tid);
        const int z = __ldg(pos_z + tid);
        const unsigned base  = (unsigned)(2 * z) * HW_ + (unsigned)y * W_ + (unsigned)x;
        const unsigned sbase = (unsigned)z * HW_ + (unsigned)y * W_ + (unsigned)x;

        // all loads independent, issued up front
        const float s0  = __ldg(scores  + base);
        const float s1  = __ldg(scores  + base + HW_);
        const float v0  = __ldg(vcoords + base);
        const float v1  = __ldg(vcoords + base + HW_);
        const float sp  = __ldg(sides   + sbase);
        const float2 vt = __ldg((const float2*)v_targets + tid);
        const float mm  = (float)__ldg(side_mask + tid);
        const float st  = __ldg(side_targets + tid);

        float vsum = smooth_l1(v0 - vt.x) + smooth_l1(v1 - vt.y);
        float osum = smooth_l1(sp - st) * mm;
        float cnt  = mm;
        cls = ce_term(s0 - s1);                          // target = 1

        #pragma unroll
        for (int off = 16; off > 0; off >>= 1) {
            vsum += __shfl_xor_sync(0xFFFFFFFFu, vsum, off);
            osum += __shfl_xor_sync(0xFFFFFFFFu, osum, off);
            cnt  += __shfl_xor_sync(0xFFFFFFFFu, cnt,  off);
            cls  += __shfl_xor_sync(0xFFFFFFFFu, cls,  off);
        }
        if ((tid & 31) == 0) {
            s_v[wid] = vsum; s_o[wid] = osum; s_c[wid] = cnt; s_cls[wid] = cls;
        }
    } else {
        // ---- negative anchor tid-64 (warps 2-3), target = 0 ----
        const int i = tid - 64;
        const int y = __ldg(neg_y + i);
        const int x = __ldg(neg_x + i);
        const int z = __ldg(neg_z + i);
        const unsigned base = (unsigned)(2 * z) * HW_ + (unsigned)y * W_ + (unsigned)x;
        const float s0 = __ldg(scores + base);
        const float s1 = __ldg(scores + base + HW_);
        cls = ce_term(s1 - s0);

        #pragma unroll
        for (int off = 16; off > 0; off >>= 1)
            cls += __shfl_xor_sync(0xFFFFFFFFu, cls, off);
        if ((tid & 31) == 0) s_cls[wid] = cls;
    }

    __syncthreads();

    if (tid == 0) {
        const float a = s_cls[0] + s_cls[1] + s_cls[2] + s_cls[3];
        const float b = s_v[0] + s_v[1];
        const float c = s_o[0] + s_o[1];
        const float d = s_c[0] + s_c[1];

        const float avg_cls = a * (1.0f / 128.0f);
        const float avg_v   = b * (1.0f / 128.0f);       // 64 anchors * 2 comps
        const float avg_o   = (d > 0.0f) ? __fdividef(c, d) : 0.0f;  // d integral >=1 when >0
        const float loss    = avg_cls + avg_v + 2.0f * avg_o;

        if (out_size >= 4) {
            *(float4*)out = make_float4(loss, avg_cls, avg_v, avg_o);
        } else {
            if (out_size > 0) out[0] = loss;
            if (out_size > 1) out[1] = avg_cls;
            if (out_size > 2) out[2] = avg_v;
            if (out_size > 3) out[3] = avg_o;
        }
    }
}

extern "C" void kernel_launch(void* const* d_in, const int* in_sizes, int n_in,
                              void* d_out, int out_size) {
    const float* scores       = (const float*)d_in[0];
    const float* vcoords      = (const float*)d_in[1];
    const float* sides        = (const float*)d_in[2];
    const int*   pos_y        = (const int*)d_in[3];
    const int*   pos_x        = (const int*)d_in[4];
    const int*   pos_z        = (const int*)d_in[5];
    const int*   neg_y        = (const int*)d_in[6];
    const int*   neg_x        = (const int*)d_in[7];
    const int*   neg_z        = (const int*)d_in[8];
    const float* v_targets    = (const float*)d_in[9];
    const int*   side_mask    = (const int*)d_in[10];
    const float* side_targets = (const float*)d_in[11];

    ctpn_loss_kernel<<<1, 128>>>(scores, vcoords, sides,
                                 pos_y, pos_x, pos_z,
                                 neg_y, neg_x, neg_z,
                                 v_targets, side_mask, side_targets,
                                 (float*)d_out, out_size);
}